// round 17
// baseline (speedup 1.0000x reference)
#include <cuda_runtime.h>
#include <cstdint>

// out[src] += feat[dst] * w    ; feat [N,64] f32, E=1e6, N=1e5
// 3-launch pipeline:
//   k_hist     : degree histogram; records each edge's within-node position
//   k_scanscat : FUSED scan+scatter. Blocks [0,NBS) do the chunk scan and
//                NEVER wait (lowest bids, all resident in wave 1 -> provably
//                deadlock-free). Blocks [NBS,...) preload their edge data,
//                wait on the scan-done counter, then scatter atomic-free.
//   k_accum    : converged 16-lane/node gather+FMA; resets counters for replay.
//
// Inputs: d_in[0]=feat f32[N*64], d_in[1]=ew f32[E],
//         d_in[2]=esrc i32[E],    d_in[3]=edst i32[E]

#define MAXN 100000
#define MAXE 1000000
#define BT 256                       // threads per block
#define NCHUNK 256                   // nodes per scan block

__device__ int      g_cnt[MAXN];     // zero at entry (zero-init; scan resets)
__device__ int2     g_desc[MAXN];    // {start, len}
__device__ int      g_pos[MAXE];     // per-edge within-node position (from hist)
__device__ float2   g_edge[MAXE];    // dense CSR payload
__device__ unsigned g_total;         // base allocator   (accum resets)
__device__ unsigned g_done_scan;     // scan blocks done (accum resets)

__global__ void k_hist(const int4* __restrict__ esrc4, int n_edges4) {
    int i = blockIdx.x * blockDim.x + threadIdx.x;
    if (i < n_edges4) {
        int4 s = __ldg(&esrc4[i]);
        int4 p;
        p.x = atomicAdd(&g_cnt[s.x], 1);
        p.y = atomicAdd(&g_cnt[s.y], 1);
        p.z = atomicAdd(&g_cnt[s.z], 1);
        p.w = atomicAdd(&g_cnt[s.w], 1);
        reinterpret_cast<int4*>(g_pos)[i] = p;   // keep returned positions
    }
}

__global__ __launch_bounds__(BT) void k_scanscat(
    const int4*   __restrict__ esrc4,
    const int4*   __restrict__ edst4,
    const float4* __restrict__ ew4,
    int n_edges4, int n, int NBS)
{
    int b = blockIdx.x, t = threadIdx.x;

    if (b < NBS) {
        // ---- scan: 256-node chunk, order-free global base. Never waits. ----
        __shared__ int warp_sum[8];
        __shared__ int s_base;
        int lane = t & 31, w = t >> 5;
        int i = b * NCHUNK + t;

        int v = 0;
        if (i < n) { v = g_cnt[i]; g_cnt[i] = 0; }

        int x = v;
        #pragma unroll
        for (int off = 1; off < 32; off <<= 1) {
            int y = __shfl_up_sync(0xffffffff, x, off);
            if (lane >= off) x += y;
        }
        if (lane == 31) warp_sum[w] = x;
        __syncthreads();

        if (w == 0) {
            int ws = (lane < 8) ? warp_sum[lane] : 0;
            int z = ws;
            #pragma unroll
            for (int off = 1; off < 8; off <<= 1) {
                int y = __shfl_up_sync(0xffffffff, z, off);
                if (lane >= off) z += y;
            }
            if (lane < 8) warp_sum[lane] = z - ws;      // exclusive warp offsets
            if (lane == 7) s_base = (int)atomicAdd(&g_total, (unsigned)z);
        }
        __syncthreads();

        if (i < n) {
            int start = s_base + warp_sum[w] + (x - v);
            g_desc[i] = make_int2(start, v);
        }

        __syncthreads();
        if (t == 0) {
            __threadfence();                            // release g_desc
            atomicAdd(&g_done_scan, 1u);
        }
    } else {
        // ---- scatter: preload inputs, wait for scan, permute atomic-free ----
        int i = (b - NBS) * BT + t;
        bool ok = (i < n_edges4);
        int4   s = make_int4(0, 0, 0, 0);
        int4   d = make_int4(0, 0, 0, 0);
        float4 w = make_float4(0.f, 0.f, 0.f, 0.f);
        int4   p = make_int4(0, 0, 0, 0);
        if (ok) {
            s = __ldg(&esrc4[i]);
            d = __ldg(&edst4[i]);
            w = __ldg(&ew4[i]);
            p = reinterpret_cast<const int4*>(g_pos)[i];  // hist output (prior launch)
        }
        if (t == 0) {
            while (*(volatile unsigned*)&g_done_scan < (unsigned)NBS)
                __nanosleep(64);
        }
        __syncthreads();
        __threadfence();                                // acquire g_desc
        if (ok) {
            g_edge[__ldg(&g_desc[s.x]).x + p.x] = make_float2(__int_as_float(d.x), w.x);
            g_edge[__ldg(&g_desc[s.y]).x + p.y] = make_float2(__int_as_float(d.y), w.y);
            g_edge[__ldg(&g_desc[s.z]).x + p.z] = make_float2(__int_as_float(d.z), w.z);
            g_edge[__ldg(&g_desc[s.w]).x + p.w] = make_float2(__int_as_float(d.w), w.w);
        }
    }
}

// 16 lanes per node, float4 lanes, unroll-2 with next-pair prefetch; 8 blk/SM.
// (Converged loop -- do not modify.) Resets build counters for next replay.
__global__ __launch_bounds__(256, 8) void k_accum(const float* __restrict__ feat,
                                                  float* __restrict__ out,
                                                  int n_nodes) {
    int gid  = blockIdx.x * blockDim.x + threadIdx.x;
    int node = gid >> 4;
    int lane = gid & 15;
    if (gid == 0) { g_total = 0; g_done_scan = 0; }
    if (node >= n_nodes) return;

    int2 dsc = __ldg(&g_desc[node]);
    int beg = dsc.x;
    int end = dsc.x + dsc.y;

    float4 acc = make_float4(0.f, 0.f, 0.f, 0.f);
    int j = beg;

    if (j + 1 < end) {
        float2 e0 = __ldg(&g_edge[j]);
        float2 e1 = __ldg(&g_edge[j + 1]);
        for (; j + 3 < end; j += 2) {
            float2 n0 = __ldg(&g_edge[j + 2]);
            float2 n1 = __ldg(&g_edge[j + 3]);
            const float4* r0 = reinterpret_cast<const float4*>(feat + (__float_as_int(e0.x) << 6));
            const float4* r1 = reinterpret_cast<const float4*>(feat + (__float_as_int(e1.x) << 6));
            float4 v0 = __ldg(&r0[lane]);
            float4 v1 = __ldg(&r1[lane]);
            acc.x += v0.x * e0.y + v1.x * e1.y;
            acc.y += v0.y * e0.y + v1.y * e1.y;
            acc.z += v0.z * e0.y + v1.z * e1.y;
            acc.w += v0.w * e0.y + v1.w * e1.y;
            e0 = n0; e1 = n1;
        }
        const float4* r0 = reinterpret_cast<const float4*>(feat + (__float_as_int(e0.x) << 6));
        const float4* r1 = reinterpret_cast<const float4*>(feat + (__float_as_int(e1.x) << 6));
        float4 v0 = __ldg(&r0[lane]);
        float4 v1 = __ldg(&r1[lane]);
        acc.x += v0.x * e0.y + v1.x * e1.y;
        acc.y += v0.y * e0.y + v1.y * e1.y;
        acc.z += v0.z * e0.y + v1.z * e1.y;
        acc.w += v0.w * e0.y + v1.w * e1.y;
        j += 2;
    }
    if (j < end) {
        float2 e0 = __ldg(&g_edge[j]);
        const float4* r0 = reinterpret_cast<const float4*>(feat + (__float_as_int(e0.x) << 6));
        float4 v0 = __ldg(&r0[lane]);
        acc.x += v0.x * e0.y;
        acc.y += v0.y * e0.y;
        acc.z += v0.z * e0.y;
        acc.w += v0.w * e0.y;
    }
    reinterpret_cast<float4*>(out + ((long long)node << 6))[lane] = acc;
}

extern "C" void kernel_launch(void* const* d_in, const int* in_sizes, int n_in,
                              void* d_out, int out_size)
{
    const float* feat = (const float*)d_in[0];
    const float* ew   = (const float*)d_in[1];
    const int*   esrc = (const int*)d_in[2];
    const int*   edst = (const int*)d_in[3];
    float*       out  = (float*)d_out;

    int n_edges  = in_sizes[1];
    int n_nodes  = out_size / 64;
    int n_edges4 = n_edges / 4;                         // E divisible by 4

    int NBS = (n_nodes + NCHUNK - 1) / NCHUNK;          // 391 scan blocks
    int S   = (n_edges4 + BT - 1) / BT;                 // 977 scatter blocks

    k_hist<<<(n_edges4 + BT - 1) / BT, BT>>>((const int4*)esrc, n_edges4);
    k_scanscat<<<NBS + S, BT>>>((const int4*)esrc, (const int4*)edst,
                                (const float4*)ew, n_edges4, n_nodes, NBS);

    long long total = (long long)n_nodes * 16;
    k_accum<<<(int)((total + 255) / 256), 256>>>(feat, out, n_nodes);
}